// round 3
// baseline (speedup 1.0000x reference)
#include <cuda_runtime.h>
#include <math.h>

#define BB 4
#define CC 128
#define NNp 32768
#define KK9 9
#define KS5 5
#define EPSb 1e-5f
#define MTOT 131072.0f   // B*N samples per BN channel
#define PROWS 2048       // conv grid size (N/64 * B)

// ---------------- scratch (device globals: no allocs allowed) ----------------
__device__ float d_xt  [(size_t)BB*NNp*CC];   // x transposed [B,N,C]
__device__ float d_bufA[(size_t)BB*NNp*CC];   // gather-conv raw output [B,N,C]
__device__ float d_bufB[(size_t)BB*NNp*CC];   // weighted-conv raw output [B,N,C]
__device__ float d_gw  [(size_t)BB*KS5*NNp];  // gaussian window weights [B,KS,N]
__device__ float d_wt  [2*KK9*CC*CC];         // w2d reordered [k][c][o], 2 blocks
__device__ float d_wct [2*KS5*CC*CC];         // wc  reordered [k][c][o], 2 blocks
__device__ float d_part[256*PROWS];           // per-CTA BN partials [col][row]
__device__ float d_colsum[256];               // reduced: [0..127]=sum, [128..255]=sumsq

// ---------------- f32x2 helpers (Blackwell packed fp32) ----------------
__device__ __forceinline__ unsigned long long ffma2(unsigned long long a,
                                                    unsigned long long b,
                                                    unsigned long long c) {
    unsigned long long d;
    asm("fma.rn.f32x2 %0, %1, %2, %3;" : "=l"(d) : "l"(a), "l"(b), "l"(c));
    return d;
}
__device__ __forceinline__ unsigned long long pack2(float x, float y) {
    unsigned long long d;
    asm("mov.b64 %0, {%1, %2};" : "=l"(d) : "f"(x), "f"(y));
    return d;
}
__device__ __forceinline__ void unpack2(unsigned long long v, float& lo, float& hi) {
    asm("mov.b64 {%0, %1}, %2;" : "=f"(lo), "=f"(hi) : "l"(v));
}

// ---------------- transpose x [B,C,N] -> xt [B,N,C] ----------------
__global__ void k_transpose(const float* __restrict__ x) {
    __shared__ float tile[32][33];
    int b = blockIdx.z, c0 = blockIdx.y * 32, n0 = blockIdx.x * 32;
    int tx = threadIdx.x, ty = threadIdx.y;
#pragma unroll
    for (int j = 0; j < 4; j++) {
        int c = c0 + ty + 8 * j;
        tile[ty + 8 * j][tx] = x[((size_t)b * CC + c) * NNp + n0 + tx];
    }
    __syncthreads();
#pragma unroll
    for (int j = 0; j < 4; j++) {
        int n = n0 + ty + 8 * j;
        d_xt[((size_t)b * NNp + n) * CC + c0 + tx] = tile[tx][ty + 8 * j];
    }
}

// ---------------- gaussian window weights ----------------
__global__ void k_gw(const float* __restrict__ co) {
    int b = blockIdx.y;
    int n = blockIdx.x * 256 + threadIdx.x;
    float c0 = co[((size_t)b * 3 + 0) * NNp + n];
    float c1 = co[((size_t)b * 3 + 1) * NNp + n];
    float c2 = co[((size_t)b * 3 + 2) * NNp + n];
#pragma unroll
    for (int k = 0; k < KS5; k++) {
        int m = n + k - 2;
        float g = 0.0f;
        if (m >= 0 && m < NNp) {
            float dx = co[((size_t)b * 3 + 0) * NNp + m] - c0;
            float dy = co[((size_t)b * 3 + 1) * NNp + m] - c1;
            float dz = co[((size_t)b * 3 + 2) * NNp + m] - c2;
            g = expf(-0.5f * (dx * dx + dy * dy + dz * dz));
        }
        d_gw[((size_t)b * KS5 + k) * NNp + n] = g;
    }
}

// ---------------- weight reorder [o][c][k] -> [k][c][o] ----------------
__global__ void k_prep(const float* __restrict__ w, int KKk, int isC, int slot) {
    float* wt = isC ? (d_wct + (size_t)slot * KS5 * CC * CC)
                    : (d_wt  + (size_t)slot * KK9 * CC * CC);
    int i = blockIdx.x * 256 + threadIdx.x;
    int tot = CC * CC * KKk;
    if (i < tot) {
        int o = i & 127;
        int c = (i >> 7) & 127;
        int k = i / (CC * CC);
        wt[i] = w[(o * CC + c) * KKk + k];
    }
}

// ---------------- BN partial reduction: part[col][*] -> colsum[col] ----------------
__global__ void k_red() {
    __shared__ float sh[256];
    int col = blockIdx.x, tid = threadIdx.x;
    const float* p = d_part + (size_t)col * PROWS;
    float s = 0.0f;
    for (int i = tid; i < PROWS; i += 256) s += p[i];
    sh[tid] = s;
    __syncthreads();
    for (int st = 128; st > 0; st >>= 1) {
        if (tid < st) sh[tid] += sh[tid + st];
        __syncthreads();
    }
    if (tid == 0) d_colsum[col] = sh[0];
}

// ---------------- gather conv (KNN) + fused input-BN+ReLU + BN stats ----------------
// y[b,n,o] = sum_{k,c} T(src[b, idx[b,n,k], c]) * w[k][c][o]  -> d_bufA (raw)
__global__ __launch_bounds__(256, 2) void k_gconv(
    int srcSel, const int* __restrict__ eidx, int wSel,
    int hasT, const float* __restrict__ gamma, const float* __restrict__ beta)
{
    extern __shared__ float sm[];
    float* Ws  = sm;                 // 16384
    float* As  = sm + 16384;         // 8192  [c][n], stride 64
    float* red = As + 8192;          // 256
    float* ssc = red + 256;          // 128
    float* ssh = ssc + 128;          // 128
    int*  sidx = (int*)(ssh + 128);  // 576

    const float* src = srcSel ? d_bufB : d_xt;
    const float* wt  = d_wt + (size_t)wSel * KK9 * CC * CC;

    int tid = threadIdx.x;
    int tx = tid & 31, ty = tid >> 5;
    int b = blockIdx.y;
    int n0 = blockIdx.x * 64;

    red[tid] = 0.0f;
    if (hasT && tid < 128) {
        float s = d_colsum[tid], q = d_colsum[128 + tid];
        float mean = s * (1.0f / MTOT);
        float var  = q * (1.0f / MTOT) - mean * mean;
        float sc   = gamma[tid] * rsqrtf(var + EPSb);
        ssc[tid] = sc;
        ssh[tid] = beta[tid] - mean * sc;
    }
    for (int i = tid; i < 64 * KK9; i += 256)
        sidx[i] = eidx[((size_t)b * NNp + n0) * KK9 + i];

    unsigned long long acc[4][4];
#pragma unroll
    for (int p = 0; p < 4; p++)
#pragma unroll
        for (int q = 0; q < 4; q++) acc[p][q] = 0ull;

    int nloc = tid & 63, ch = tid >> 6;

    for (int k = 0; k < KK9; k++) {
        __syncthreads();
        // stage weight k-slice [c][o]
        {
            const float4* s4 = (const float4*)(wt + k * CC * CC);
            float4* dst4 = (float4*)Ws;
#pragma unroll
            for (int u = 0; u < 16; u++) dst4[tid + u * 256] = s4[tid + u * 256];
        }
        // gather A-tile: As[c][n] = T(src[b, idx[n,k], c])
        {
            int j = sidx[nloc * KK9 + k];
            const float4* s4 = (const float4*)(src + ((size_t)b * NNp + j) * CC + ch * 32);
#pragma unroll
            for (int u = 0; u < 8; u++) {
                float4 v = s4[u];
                int c = ch * 32 + u * 4;
                if (hasT) {
                    v.x = fmaxf(0.0f, ssc[c + 0] * v.x + ssh[c + 0]);
                    v.y = fmaxf(0.0f, ssc[c + 1] * v.y + ssh[c + 1]);
                    v.z = fmaxf(0.0f, ssc[c + 2] * v.z + ssh[c + 2]);
                    v.w = fmaxf(0.0f, ssc[c + 3] * v.w + ssh[c + 3]);
                }
                As[(c + 0) * 64 + nloc] = v.x;
                As[(c + 1) * 64 + nloc] = v.y;
                As[(c + 2) * 64 + nloc] = v.z;
                As[(c + 3) * 64 + nloc] = v.w;
            }
        }
        __syncthreads();
#pragma unroll 8
        for (int c = 0; c < CC; c++) {
            float4 w4 = *(const float4*)(Ws + c * CC + (tx << 2));
            unsigned long long wd0 = pack2(w4.x, w4.x);
            unsigned long long wd1 = pack2(w4.y, w4.y);
            unsigned long long wd2 = pack2(w4.z, w4.z);
            unsigned long long wd3 = pack2(w4.w, w4.w);
            const ulonglong2* ap = (const ulonglong2*)(As + c * 64 + (ty << 3));
            ulonglong2 aA = ap[0], aB = ap[1];
            unsigned long long av[4] = {aA.x, aA.y, aB.x, aB.y};
#pragma unroll
            for (int p = 0; p < 4; p++) {
                acc[p][0] = ffma2(av[p], wd0, acc[p][0]);
                acc[p][1] = ffma2(av[p], wd1, acc[p][1]);
                acc[p][2] = ffma2(av[p], wd2, acc[p][2]);
                acc[p][3] = ffma2(av[p], wd3, acc[p][3]);
            }
        }
    }
    // epilogue: store raw output + BN stats
    float s[4] = {0, 0, 0, 0}, q2[4] = {0, 0, 0, 0};
#pragma unroll
    for (int p = 0; p < 4; p++) {
        float lo[4], hi[4];
#pragma unroll
        for (int oi = 0; oi < 4; oi++) {
            unpack2(acc[p][oi], lo[oi], hi[oi]);
            s[oi]  += lo[oi] + hi[oi];
            q2[oi] += lo[oi] * lo[oi] + hi[oi] * hi[oi];
        }
        size_t base = ((size_t)b * NNp + n0 + (ty << 3) + 2 * p) * CC + (tx << 2);
        *(float4*)(d_bufA + base)      = make_float4(lo[0], lo[1], lo[2], lo[3]);
        *(float4*)(d_bufA + base + CC) = make_float4(hi[0], hi[1], hi[2], hi[3]);
    }
#pragma unroll
    for (int oi = 0; oi < 4; oi++) {
        atomicAdd(&red[(tx << 2) + oi], s[oi]);
        atomicAdd(&red[128 + (tx << 2) + oi], q2[oi]);
    }
    __syncthreads();
    int row = blockIdx.y * gridDim.x + blockIdx.x;
    if (tid < 128) {
        d_part[(size_t)tid * PROWS + row]          = red[tid];
        d_part[(size_t)(128 + tid) * PROWS + row]  = red[128 + tid];
    }
}

// ---------------- gaussian-weighted conv1d + fused BN+ReLU + BN stats ----------------
// y[b,n,o] = sum_k gw[b,k,n] * sum_c relu(BN(bufA[b,n+k-2,c])) * wc[k][c][o] -> d_bufB
__global__ __launch_bounds__(256, 2) void k_wconv(
    int wSel, const float* __restrict__ gamma, const float* __restrict__ beta)
{
    extern __shared__ float sm[];
    float* Ws  = sm;                 // 16384
    float* Zk  = sm + 16384;         // 8192  [c][n], gw folded in
    float* red = Zk + 8192;          // 256
    float* ssc = red + 256;          // 128
    float* ssh = ssc + 128;          // 128

    const float* wt = d_wct + (size_t)wSel * KS5 * CC * CC;

    int tid = threadIdx.x;
    int tx = tid & 31, ty = tid >> 5;
    int b = blockIdx.y;
    int n0 = blockIdx.x * 64;

    red[tid] = 0.0f;
    if (tid < 128) {
        float s = d_colsum[tid], q = d_colsum[128 + tid];
        float mean = s * (1.0f / MTOT);
        float var  = q * (1.0f / MTOT) - mean * mean;
        float sc   = gamma[tid] * rsqrtf(var + EPSb);
        ssc[tid] = sc;
        ssh[tid] = beta[tid] - mean * sc;
    }

    unsigned long long acc[4][4];
#pragma unroll
    for (int p = 0; p < 4; p++)
#pragma unroll
        for (int q = 0; q < 4; q++) acc[p][q] = 0ull;

    int nloc = tid & 63, ch = tid >> 6;

    for (int k = 0; k < KS5; k++) {
        __syncthreads();
        {
            const float4* s4 = (const float4*)(wt + k * CC * CC);
            float4* dst4 = (float4*)Ws;
#pragma unroll
            for (int u = 0; u < 16; u++) dst4[tid + u * 256] = s4[tid + u * 256];
        }
        // build Zk[c][n] = gw[k][n] * relu(BN(bufA[n+k-2][c]))  (zero outside range)
        {
            int m = n0 + nloc + k - 2;
            float g = d_gw[((size_t)b * KS5 + k) * NNp + n0 + nloc];
            bool valid = (m >= 0 && m < NNp);
            const float4* s4 = (const float4*)(d_bufA + ((size_t)b * NNp + (valid ? m : 0)) * CC + ch * 32);
#pragma unroll
            for (int u = 0; u < 8; u++) {
                int c = ch * 32 + u * 4;
                float z0 = 0.0f, z1 = 0.0f, z2 = 0.0f, z3 = 0.0f;
                if (valid) {
                    float4 v = s4[u];
                    z0 = fmaxf(0.0f, ssc[c + 0] * v.x + ssh[c + 0]) * g;
                    z1 = fmaxf(0.0f, ssc[c + 1] * v.y + ssh[c + 1]) * g;
                    z2 = fmaxf(0.0f, ssc[c + 2] * v.z + ssh[c + 2]) * g;
                    z3 = fmaxf(0.0f, ssc[c + 3] * v.w + ssh[c + 3]) * g;
                }
                Zk[(c + 0) * 64 + nloc] = z0;
                Zk[(c + 1) * 64 + nloc] = z1;
                Zk[(c + 2) * 64 + nloc] = z2;
                Zk[(c + 3) * 64 + nloc] = z3;
            }
        }
        __syncthreads();
#pragma unroll 8
        for (int c = 0; c < CC; c++) {
            float4 w4 = *(const float4*)(Ws + c * CC + (tx << 2));
            unsigned long long wd0 = pack2(w4.x, w4.x);
            unsigned long long wd1 = pack2(w4.y, w4.y);
            unsigned long long wd2 = pack2(w4.z, w4.z);
            unsigned long long wd3 = pack2(w4.w, w4.w);
            const ulonglong2* ap = (const ulonglong2*)(Zk + c * 64 + (ty << 3));
            ulonglong2 aA = ap[0], aB = ap[1];
            unsigned long long av[4] = {aA.x, aA.y, aB.x, aB.y};
#pragma unroll
            for (int p = 0; p < 4; p++) {
                acc[p][0] = ffma2(av[p], wd0, acc[p][0]);
                acc[p][1] = ffma2(av[p], wd1, acc[p][1]);
                acc[p][2] = ffma2(av[p], wd2, acc[p][2]);
                acc[p][3] = ffma2(av[p], wd3, acc[p][3]);
            }
        }
    }
    float s[4] = {0, 0, 0, 0}, q2[4] = {0, 0, 0, 0};
#pragma unroll
    for (int p = 0; p < 4; p++) {
        float lo[4], hi[4];
#pragma unroll
        for (int oi = 0; oi < 4; oi++) {
            unpack2(acc[p][oi], lo[oi], hi[oi]);
            s[oi]  += lo[oi] + hi[oi];
            q2[oi] += lo[oi] * lo[oi] + hi[oi] * hi[oi];
        }
        size_t base = ((size_t)b * NNp + n0 + (ty << 3) + 2 * p) * CC + (tx << 2);
        *(float4*)(d_bufB + base)      = make_float4(lo[0], lo[1], lo[2], lo[3]);
        *(float4*)(d_bufB + base + CC) = make_float4(hi[0], hi[1], hi[2], hi[3]);
    }
#pragma unroll
    for (int oi = 0; oi < 4; oi++) {
        atomicAdd(&red[(tx << 2) + oi], s[oi]);
        atomicAdd(&red[128 + (tx << 2) + oi], q2[oi]);
    }
    __syncthreads();
    int row = blockIdx.y * gridDim.x + blockIdx.x;
    if (tid < 128) {
        d_part[(size_t)tid * PROWS + row]          = red[tid];
        d_part[(size_t)(128 + tid) * PROWS + row]  = red[128 + tid];
    }
}

// ---------------- final: out = relu(BN2b(bufB) + x), transposed to [B,C,N] ----------------
__global__ void k_final(const float* __restrict__ x,
                        const float* __restrict__ gamma,
                        const float* __restrict__ beta,
                        float* __restrict__ out)
{
    __shared__ float tile[32][33];
    __shared__ float sc[32], sh[32];
    int b = blockIdx.z, c0 = blockIdx.y * 32, n0 = blockIdx.x * 32;
    int tx = threadIdx.x, ty = threadIdx.y;
    if (ty == 0) {
        int c = c0 + tx;
        float s = d_colsum[c], q = d_colsum[128 + c];
        float mean = s * (1.0f / MTOT);
        float var  = q * (1.0f / MTOT) - mean * mean;
        float a = gamma[c] * rsqrtf(var + EPSb);
        sc[tx] = a;
        sh[tx] = beta[c] - mean * a;
    }
    __syncthreads();
#pragma unroll
    for (int j = 0; j < 4; j++) {
        int n = n0 + ty + 8 * j;
        float v = d_bufB[((size_t)b * NNp + n) * CC + c0 + tx];
        tile[ty + 8 * j][tx] = sc[tx] * v + sh[tx];
    }
    __syncthreads();
#pragma unroll
    for (int j = 0; j < 4; j++) {
        int c = c0 + ty + 8 * j;
        size_t o = ((size_t)b * CC + c) * NNp + n0 + tx;
        out[o] = fmaxf(0.0f, tile[tx][ty + 8 * j] + x[o]);
    }
}

// ---------------- launch ----------------
extern "C" void kernel_launch(void* const* d_in, const int* in_sizes, int n_in,
                              void* d_out, int out_size)
{
    const float* x    = (const float*)d_in[0];
    const int*   ei   = (const int*)d_in[1];
    const float* co   = (const float*)d_in[2];
    const float* w2d1 = (const float*)d_in[3];
    const float* g2d1 = (const float*)d_in[4];
    const float* b2d1 = (const float*)d_in[5];
    const float* wc1  = (const float*)d_in[6];
    const float* g1d1 = (const float*)d_in[7];
    const float* b1d1 = (const float*)d_in[8];
    const float* w2d2 = (const float*)d_in[9];
    const float* g2d2 = (const float*)d_in[10];
    const float* b2d2 = (const float*)d_in[11];
    const float* wc2  = (const float*)d_in[12];
    const float* g1d2 = (const float*)d_in[13];
    const float* b1d2 = (const float*)d_in[14];
    float* out = (float*)d_out;

    const int smemG = (16384 + 8192 + 256 + 128 + 128) * 4 + 576 * 4;  // 102656
    const int smemW = (16384 + 8192 + 256 + 128 + 128) * 4;            // 100352
    cudaFuncSetAttribute(k_gconv, cudaFuncAttributeMaxDynamicSharedMemorySize, smemG);
    cudaFuncSetAttribute(k_wconv, cudaFuncAttributeMaxDynamicSharedMemorySize, smemW);

    k_transpose<<<dim3(NNp / 32, CC / 32, BB), dim3(32, 8)>>>(x);
    k_gw<<<dim3(NNp / 256, BB), 256>>>(co);
    k_prep<<<(CC * CC * KK9 + 255) / 256, 256>>>(w2d1, KK9, 0, 0);
    k_prep<<<(CC * CC * KK9 + 255) / 256, 256>>>(w2d2, KK9, 0, 1);
    k_prep<<<(CC * CC * KS5 + 255) / 256, 256>>>(wc1, KS5, 1, 0);
    k_prep<<<(CC * CC * KS5 + 255) / 256, 256>>>(wc2, KS5, 1, 1);

    dim3 gconv(NNp / 64, BB);
    // block 1
    k_gconv<<<gconv, 256, smemG>>>(0, ei, 0, 0, (const float*)0, (const float*)0);
    k_red<<<256, 256>>>();
    k_wconv<<<gconv, 256, smemW>>>(0, g2d1, b2d1);
    k_red<<<256, 256>>>();
    // block 2
    k_gconv<<<gconv, 256, smemG>>>(1, ei, 1, 1, g1d1, b1d1);
    k_red<<<256, 256>>>();
    k_wconv<<<gconv, 256, smemW>>>(1, g2d2, b2d2);
    k_red<<<256, 256>>>();
    // residual + relu
    k_final<<<dim3(NNp / 32, CC / 32, BB), dim3(32, 8)>>>(x, g1d2, b1d2, out);
}

// round 7
// speedup vs baseline: 1.3496x; 1.3496x over previous
#include <cuda_runtime.h>
#include <cuda_bf16.h>
#include <math.h>
#include <stdint.h>

#define BB 4
#define CC 128
#define NNp 32768
#define KK9 9
#define KS5 5
#define EPSb 1e-5f
#define MTOT 131072.0f
#define PROWS 1024            // grid = 256 n-tiles x 4 batches

// ---------------- scratch (device globals: no allocs allowed) ----------------
__device__ float d_xt  [(size_t)BB*NNp*CC];   // x transposed [B,N,C]
__device__ float d_bufA[(size_t)BB*NNp*CC];
__device__ float d_bufB[(size_t)BB*NNp*CC];
__device__ float d_gw  [(size_t)BB*KS5*NNp];  // gaussian weights [B,KS,N]
__device__ __nv_bfloat16 d_wg[(size_t)2*KK9*2*16384]; // gconv W planes [slot][k][hi/lo][o][c]
__device__ __nv_bfloat16 d_wc[(size_t)2*KS5*2*16384]; // wconv W planes
__device__ float d_part[256*PROWS];
__device__ float d_colsum[256];

// ---------------- helpers ----------------
__device__ __forceinline__ uint32_t smem_u32(const void* p) {
    uint32_t a;
    asm("{ .reg .u64 t; cvta.to.shared.u64 t, %1; cvt.u32.u64 %0, t; }" : "=r"(a) : "l"(p));
    return a;
}
__device__ __forceinline__ uint32_t pack_bf2(float x, float y) {
    __nv_bfloat162 t = __floats2bfloat162_rn(x, y);
    return *(uint32_t*)&t;
}

#define LDSM4(r, addr) \
    asm volatile("ldmatrix.sync.aligned.m8n8.x4.shared.b16 {%0,%1,%2,%3}, [%4];" \
        : "=r"((r)[0]), "=r"((r)[1]), "=r"((r)[2]), "=r"((r)[3]) : "r"(addr))
#define LDSM2(r, addr) \
    asm volatile("ldmatrix.sync.aligned.m8n8.x2.shared.b16 {%0,%1}, [%2];" \
        : "=r"((r)[0]), "=r"((r)[1]) : "r"(addr))
#define MMA_BF16(d, a, b) \
    asm volatile("mma.sync.aligned.m16n8k16.row.col.f32.bf16.bf16.f32 " \
        "{%0,%1,%2,%3}, {%4,%5,%6,%7}, {%8,%9}, {%0,%1,%2,%3};" \
        : "+f"((d)[0]), "+f"((d)[1]), "+f"((d)[2]), "+f"((d)[3]) \
        : "r"((a)[0]), "r"((a)[1]), "r"((a)[2]), "r"((a)[3]), "r"((b)[0]), "r"((b)[1]))

// SMEM layout (bytes). bf16 rows padded to 136 elems = 272 B (conflict-free ldmatrix)
#define SA_H 0
#define SA_L 34816
#define SW_H 69632
#define SW_L 104448
#define S_RED 139264          // 256 floats
#define S_SC  140288          // 128 floats
#define S_SH  140800          // 128 floats
#define SMEM_TOTAL 141312

// ---------------- transpose x [B,C,N] -> xt [B,N,C] ----------------
__global__ void k_transpose(const float* __restrict__ x) {
    __shared__ float tile[32][33];
    int b = blockIdx.z, c0 = blockIdx.y * 32, n0 = blockIdx.x * 32;
    int tx = threadIdx.x, ty = threadIdx.y;
#pragma unroll
    for (int j = 0; j < 4; j++)
        tile[ty + 8*j][tx] = x[((size_t)b*CC + c0 + ty + 8*j)*NNp + n0 + tx];
    __syncthreads();
#pragma unroll
    for (int j = 0; j < 4; j++)
        d_xt[((size_t)b*NNp + n0 + ty + 8*j)*CC + c0 + tx] = tile[tx][ty + 8*j];
}

// ---------------- gaussian window weights ----------------
__global__ void k_gw(const float* __restrict__ co) {
    int b = blockIdx.y;
    int n = blockIdx.x * 256 + threadIdx.x;
    float c0 = co[((size_t)b*3 + 0)*NNp + n];
    float c1 = co[((size_t)b*3 + 1)*NNp + n];
    float c2 = co[((size_t)b*3 + 2)*NNp + n];
#pragma unroll
    for (int k = 0; k < KS5; k++) {
        int m = n + k - 2;
        float g = 0.0f;
        if (m >= 0 && m < NNp) {
            float dx = co[((size_t)b*3 + 0)*NNp + m] - c0;
            float dy = co[((size_t)b*3 + 1)*NNp + m] - c1;
            float dz = co[((size_t)b*3 + 2)*NNp + m] - c2;
            g = expf(-0.5f * (dx*dx + dy*dy + dz*dz));
        }
        d_gw[((size_t)b*KS5 + k)*NNp + n] = g;
    }
}

// -------- weight prep: [o][c][k] fp32 -> [k][hi/lo][o][c] bf16 planes --------
__global__ void k_prepW(const float* __restrict__ w, int KK, int isC, int slot) {
    int i = blockIdx.x * 256 + threadIdx.x;
    if (i >= KK * 16384) return;
    int k = i >> 14;
    int rem = i & 16383;
    int o = rem >> 7, c = rem & 127;
    float v = w[((size_t)o*CC + c)*KK + k];
    __nv_bfloat16 bh = __float2bfloat16(v);
    float hf = __bfloat162float(bh);
    __nv_bfloat16 bl = __float2bfloat16(v - hf);
    __nv_bfloat16* base = (isC ? d_wc : d_wg) + ((size_t)slot*KK*2 + (size_t)k*2) * 16384;
    base[rem] = bh;
    base[16384 + rem] = bl;
}

// ---------------- BN partial reduction ----------------
__global__ void k_red() {
    __shared__ float sh[256];
    int col = blockIdx.x, tid = threadIdx.x;
    const float* p = d_part + (size_t)col * PROWS;
    float s = 0.0f;
    for (int i = tid; i < PROWS; i += 256) s += p[i];
    sh[tid] = s;
    __syncthreads();
    for (int st = 128; st > 0; st >>= 1) {
        if (tid < st) sh[tid] += sh[tid + st];
        __syncthreads();
    }
    if (tid == 0) d_colsum[col] = sh[0];
}

// ---------------- bf16x3 mma.sync GEMM (gather-conv or weighted-conv) ----------------
// mode 0: A row = T(src[b, eidx[b,n,k], :]), taps KK9
// mode 1: A row = gw[b,k,n] * T(src[b, n+k-2, :]), taps KS5
// T = relu(BN(.)) when hasT. Output raw conv result [B,N,C] + fused BN stats.
__global__ __launch_bounds__(512, 1) void k_mma(
    int mode, int srcSel, const int* __restrict__ eidx, int wSel, int KK,
    int hasT, const float* __restrict__ gamma, const float* __restrict__ beta,
    int outSel)
{
    extern __shared__ char smem[];
    float* red = (float*)(smem + S_RED);
    float* ssc = (float*)(smem + S_SC);
    float* ssh = (float*)(smem + S_SH);

    int tid = threadIdx.x;
    int lane = tid & 31, wid = tid >> 5;
    int wm = wid & 3, wo = wid >> 2;      // warp tile: rows wm*32, cols wo*32
    int b = blockIdx.y;
    int n0 = blockIdx.x * 128;

    const float* src = (srcSel == 0) ? d_xt : (srcSel == 1 ? d_bufA : d_bufB);
    const __nv_bfloat16* wbase = (mode ? d_wc : d_wg) + ((size_t)wSel * KK * 2) * 16384;
    float* outb = outSel ? d_bufB : d_bufA;

    if (tid < 256) red[tid] = 0.0f;
    if (hasT && tid < 128) {
        float s = d_colsum[tid], q = d_colsum[128 + tid];
        float mean = s * (1.0f / MTOT);
        float var  = q * (1.0f / MTOT) - mean * mean;
        float sc   = gamma[tid] * rsqrtf(var + EPSb);
        ssc[tid] = sc;
        ssh[tid] = beta[tid] - mean * sc;
    }

    float acc[2][4][4];
#pragma unroll
    for (int mt = 0; mt < 2; mt++)
#pragma unroll
        for (int ot = 0; ot < 4; ot++)
#pragma unroll
            for (int q = 0; q < 4; q++) acc[mt][ot][q] = 0.0f;

    // ldmatrix per-lane byte offsets (within plane)
    uint32_t aOff = (uint32_t)(wm*32 + (lane & 15)) * 272 + ((lane >> 4) * 16);
    uint32_t bOff = (uint32_t)(wo*32 + (lane & 7)) * 272 + (((lane >> 3) & 1) * 16);
    uint32_t ahB = smem_u32(smem + SA_H), alB = smem_u32(smem + SA_L);
    uint32_t whB = smem_u32(smem + SW_H), wlB = smem_u32(smem + SW_L);

    int r = tid >> 2;        // staging row 0..127
    int h = tid & 3;         // 32-channel block

    for (int k = 0; k < KK; k++) {
        __syncthreads();
        // ---- stage W planes (straight copy with 272B-padded rows) ----
        {
            const __nv_bfloat16* whi = wbase + (size_t)k * 2 * 16384;
            const uint4* sh4 = (const uint4*)(whi + r*128 + h*32);
            const uint4* sl4 = (const uint4*)(whi + 16384 + r*128 + h*32);
            uint4* dh = (uint4*)(smem + SW_H + r*272 + h*64);
            uint4* dl = (uint4*)(smem + SW_L + r*272 + h*64);
#pragma unroll
            for (int u = 0; u < 4; u++) { dh[u] = sh4[u]; dl[u] = sl4[u]; }
        }
        // ---- stage A: gather/shift + transform + bf16 hi/lo split ----
        {
            const float* srow;
            float g = 1.0f;
            bool valid = true;
            if (mode == 0) {
                int j = eidx[((size_t)b*NNp + n0 + r)*KK9 + k];
                srow = src + ((size_t)b*NNp + j)*CC + h*32;
            } else {
                int m = n0 + r + k - 2;
                valid = (m >= 0) && (m < NNp);
                g = d_gw[((size_t)b*KS5 + k)*NNp + n0 + r];
                srow = src + ((size_t)b*NNp + (valid ? m : 0))*CC + h*32;
            }
            uint32_t hw[16], lw[16];
#pragma unroll
            for (int u = 0; u < 8; u++) {
                float4 v = ((const float4*)srow)[u];
                float z[4] = {v.x, v.y, v.z, v.w};
                int c = h*32 + u*4;
#pragma unroll
                for (int e = 0; e < 4; e++) {
                    float zz = z[e];
                    if (hasT) zz = fmaxf(0.0f, ssc[c + e]*zz + ssh[c + e]);
                    if (mode) zz = valid ? zz * g : 0.0f;
                    z[e] = zz;
                }
                float zh[4], zl[4];
#pragma unroll
                for (int e = 0; e < 4; e++) {
                    __nv_bfloat16 bh = __float2bfloat16(z[e]);
                    zh[e] = __bfloat162float(bh);
                    zl[e] = z[e] - zh[e];
                }
                hw[u*2 + 0] = pack_bf2(zh[0], zh[1]);
                hw[u*2 + 1] = pack_bf2(zh[2], zh[3]);
                lw[u*2 + 0] = pack_bf2(zl[0], zl[1]);
                lw[u*2 + 1] = pack_bf2(zl[2], zl[3]);
            }
            uint4* dh = (uint4*)(smem + SA_H + r*272 + h*64);
            uint4* dl = (uint4*)(smem + SA_L + r*272 + h*64);
#pragma unroll
            for (int u = 0; u < 4; u++) {
                dh[u] = make_uint4(hw[u*4+0], hw[u*4+1], hw[u*4+2], hw[u*4+3]);
                dl[u] = make_uint4(lw[u*4+0], lw[u*4+1], lw[u*4+2], lw[u*4+3]);
            }
        }
        __syncthreads();
        // ---- compute: 8 k16-steps over the 128-channel contraction ----
#pragma unroll
        for (int kk = 0; kk < 8; kk++) {
            uint32_t ko = kk * 32;
            uint32_t ah[2][4], al[2][4], bh[4][2], bl[4][2];
#pragma unroll
            for (int mt = 0; mt < 2; mt++) {
                LDSM4(ah[mt], ahB + aOff + mt*4352 + ko);
                LDSM4(al[mt], alB + aOff + mt*4352 + ko);
            }
#pragma unroll
            for (int ot = 0; ot < 4; ot++) {
                LDSM2(bh[ot], whB + bOff + ot*2176 + ko);
                LDSM2(bl[ot], wlB + bOff + ot*2176 + ko);
            }
#pragma unroll
            for (int mt = 0; mt < 2; mt++)
#pragma unroll
                for (int ot = 0; ot < 4; ot++) {
                    MMA_BF16(acc[mt][ot], ah[mt], bh[ot]);
                    MMA_BF16(acc[mt][ot], ah[mt], bl[ot]);
                    MMA_BF16(acc[mt][ot], al[mt], bh[ot]);
                }
        }
    }

    // ---- epilogue: store raw output + fused BN stats ----
#pragma unroll
    for (int ot = 0; ot < 4; ot++) {
        float s0 = 0.f, s1 = 0.f, q0 = 0.f, q1 = 0.f;
        int og = wo*32 + ot*8 + 2*(lane & 3);
#pragma unroll
        for (int mt = 0; mt < 2; mt++) {
            float c0 = acc[mt][ot][0], c1 = acc[mt][ot][1];
            float c2 = acc[mt][ot][2], c3 = acc[mt][ot][3];
            int n1 = n0 + wm*32 + mt*16 + (lane >> 2);
            float* o1 = outb + ((size_t)b*NNp + n1)*CC + og;
            *(float2*)o1          = make_float2(c0, c1);
            *(float2*)(o1 + 8*CC) = make_float2(c2, c3);
            s0 += c0 + c2;  s1 += c1 + c3;
            q0 += c0*c0 + c2*c2;  q1 += c1*c1 + c3*c3;
        }
#pragma unroll
        for (int m2 = 4; m2 <= 16; m2 <<= 1) {
            s0 += __shfl_xor_sync(0xffffffffu, s0, m2);
            s1 += __shfl_xor_sync(0xffffffffu, s1, m2);
            q0 += __shfl_xor_sync(0xffffffffu, q0, m2);
            q1 += __shfl_xor_sync(0xffffffffu, q1, m2);
        }
        if (lane < 4) {
            int o4 = wo*32 + ot*8 + 2*lane;
            atomicAdd(&red[o4],     s0);
            atomicAdd(&red[o4 + 1], s1);
            atomicAdd(&red[128 + o4],     q0);
            atomicAdd(&red[128 + o4 + 1], q1);
        }
    }
    __syncthreads();
    int row = blockIdx.y * gridDim.x + blockIdx.x;
    if (tid < 256) d_part[(size_t)tid * PROWS + row] = red[tid];
}

// ---------------- final: out = relu(BN(bufB) + x), back to [B,C,N] ----------------
__global__ void k_final(const float* __restrict__ x,
                        const float* __restrict__ gamma,
                        const float* __restrict__ beta,
                        float* __restrict__ out)
{
    __shared__ float tile[32][33];
    __shared__ float sc[32], sh[32];
    int b = blockIdx.z, c0 = blockIdx.y * 32, n0 = blockIdx.x * 32;
    int tx = threadIdx.x, ty = threadIdx.y;
    if (ty == 0) {
        int c = c0 + tx;
        float s = d_colsum[c], q = d_colsum[128 + c];
        float mean = s * (1.0f / MTOT);
        float var  = q * (1.0f / MTOT) - mean * mean;
        float a = gamma[c] * rsqrtf(var + EPSb);
        sc[tx] = a;
        sh[tx] = beta[c] - mean * a;
    }
    __syncthreads();
#pragma unroll
    for (int j = 0; j < 4; j++) {
        int n = n0 + ty + 8*j;
        float v = d_bufB[((size_t)b*NNp + n)*CC + c0 + tx];
        tile[ty + 8*j][tx] = sc[tx]*v + sh[tx];
    }
    __syncthreads();
#pragma unroll
    for (int j = 0; j < 4; j++) {
        int c = c0 + ty + 8*j;
        size_t o = ((size_t)b*CC + c)*NNp + n0 + tx;
        out[o] = fmaxf(0.0f, tile[tx][ty + 8*j] + x[o]);
    }
}

// ---------------- launch ----------------
extern "C" void kernel_launch(void* const* d_in, const int* in_sizes, int n_in,
                              void* d_out, int out_size)
{
    const float* x    = (const float*)d_in[0];
    const int*   ei   = (const int*)d_in[1];
    const float* co   = (const float*)d_in[2];
    const float* w2d1 = (const float*)d_in[3];
    const float* g2d1 = (const float*)d_in[4];
    const float* b2d1 = (const float*)d_in[5];
    const float* wc1  = (const float*)d_in[6];
    const float* g1d1 = (const float*)d_in[7];
    const float* b1d1 = (const float*)d_in[8];
    const float* w2d2 = (const float*)d_in[9];
    const float* g2d2 = (const float*)d_in[10];
    const float* b2d2 = (const float*)d_in[11];
    const float* wc2  = (const float*)d_in[12];
    const float* g1d2 = (const float*)d_in[13];
    const float* b1d2 = (const float*)d_in[14];
    float* out = (float*)d_out;

    cudaFuncSetAttribute(k_mma, cudaFuncAttributeMaxDynamicSharedMemorySize, SMEM_TOTAL);

    dim3 g(NNp / 128, BB);

    // 5 pre-launches so launch #6 (ncu -s 5 -c 1) is the first heavy GEMM
    k_transpose<<<dim3(NNp/32, CC/32, BB), dim3(32, 8)>>>(x);
    k_gw<<<dim3(NNp/256, BB), 256>>>(co);
    k_prepW<<<(KK9*16384 + 255)/256, 256>>>(w2d1, KK9, 0, 0);
    k_prepW<<<(KS5*16384 + 255)/256, 256>>>(wc1,  KS5, 1, 0);
    k_prepW<<<(KK9*16384 + 255)/256, 256>>>(w2d2, KK9, 0, 1);

    // block 1
    k_mma<<<g, 512, SMEM_TOTAL>>>(0, 0, ei, 0, KK9, 0, (const float*)0, (const float*)0, 0); // gconv1 -> bufA
    k_prepW<<<(KS5*16384 + 255)/256, 256>>>(wc2, KS5, 1, 1);
    k_red<<<256, 256>>>();
    k_mma<<<g, 512, SMEM_TOTAL>>>(1, 1, ei, 0, KS5, 1, g2d1, b2d1, 1);  // wconv1: bufA -> bufB
    k_red<<<256, 256>>>();
    // block 2
    k_mma<<<g, 512, SMEM_TOTAL>>>(0, 2, ei, 1, KK9, 1, g1d1, b1d1, 0);  // gconv2: bufB -> bufA
    k_red<<<256, 256>>>();
    k_mma<<<g, 512, SMEM_TOTAL>>>(1, 1, ei, 1, KS5, 1, g2d2, b2d2, 1);  // wconv2: bufA -> bufB
    k_red<<<256, 256>>>();
    // residual + relu + transpose back
    k_final<<<dim3(NNp/32, CC/32, BB), dim3(32, 8)>>>(x, g1d2, b1d2, out);
}